// round 5
// baseline (speedup 1.0000x reference)
#include <cuda_runtime.h>
#include <math.h>

#define NN 20000
#define KK 16
#define DD 128
#define HH 256
#define FF 384

// scratch (allocation-free rule: __device__ globals)
__device__ float g_incoming[NN * DD];
__device__ float g_outgoing[NN * DD];

// ---------- f32x2 helpers (sm_103a packed fp32 pipe) ----------
__device__ __forceinline__ unsigned long long pack2(float x, float y) {
    unsigned long long r;
    asm("mov.b64 %0, {%1, %2};" : "=l"(r) : "f"(x), "f"(y));
    return r;
}
__device__ __forceinline__ void unpack2(unsigned long long a, float& x, float& y) {
    asm("mov.b64 {%0, %1}, %2;" : "=f"(x), "=f"(y) : "l"(a));
}
__device__ __forceinline__ void fma2(unsigned long long& d, unsigned long long a, unsigned long long b) {
    asm("fma.rn.f32x2 %0, %1, %2, %0;" : "+l"(d) : "l"(a), "l"(b));
}

__device__ __forceinline__ float gelu_tanh(float x) {
    float x3 = x * x * x;
    return 0.5f * x * (1.0f + tanhf(0.7978845608028654f * (x + 0.044715f * x3)));
}
__device__ __forceinline__ float sigm(float x) {
    return 1.0f / (1.0f + expf(-x));
}

// ---------------------------------------------------------------
// zero the outgoing scatter buffer every launch (deterministic)
// ---------------------------------------------------------------
__global__ void zero_kernel() {
    int i = blockIdx.x * blockDim.x + threadIdx.x;
    if (i < NN * DD) g_outgoing[i] = 0.0f;
}

// ---------------------------------------------------------------
// Pair kernel: 1 CTA (256 threads) per node (16 neighbour rows)
// ---------------------------------------------------------------
__global__ void __launch_bounds__(256, 2) pair_kernel(
    const float* __restrict__ local, const float* __restrict__ pair,
    const int*   __restrict__ nbrs,  const float* __restrict__ mask,
    const float* __restrict__ Wg,  const float* __restrict__ bg,
    const float* __restrict__ Wv,  const float* __restrict__ bv,
    const float* __restrict__ Wo,  const float* __restrict__ bo,
    const float* __restrict__ gp,  const float* __restrict__ bp,
    const float* __restrict__ Win, const float* __restrict__ Wou,
    float* __restrict__ out)
{
    // xs: transposed per-row features, 256 k-rows x 16 rows (pair block + nbr block)
    __shared__ __align__(16) float xs[256 * 16];   // 16 KB
    __shared__ float lvec[128];                    // center local (shared across rows)
    __shared__ __align__(16) float hs[256 * 16];   // hidden, 16 KB
    __shared__ float us[16 * 128];                 // u, then pu in-place
    __shared__ int   snbr[16];
    __shared__ float svalid[16];

    const int t = threadIdx.x;
    const int n = blockIdx.x;

    if (t < KK) {
        int nb = nbrs[n * KK + t];
        snbr[t] = nb;
        svalid[t] = (nb != -1 && mask[nb < 0 ? nb + NN : nb] > 0.0f) ? 1.0f : 0.0f;
    }
    if (t >= 32 && t < 160) lvec[t - 32] = local[n * DD + (t - 32)];
    __syncthreads();

    // gather: k2<128 -> pair[n][r][k2]; k2>=128 -> local[nbr[r]][k2-128]
    for (int i = t; i < 256 * 16; i += 256) {
        int k2 = i & 255;
        int r  = i >> 8;
        float v;
        if (k2 < 128) {
            v = pair[(n * KK + r) * DD + k2];
        } else {
            int nb = snbr[r];
            if (nb < 0) nb += NN;           // mimic python negative-index wrap
            v = local[nb * DD + (k2 - 128)];
        }
        xs[k2 * 16 + r] = v;
    }
    __syncthreads();

    // ---------------- GEMM1: g/v hidden pre-activations -----------------
    // thread t owns hidden column c = t for all 16 rows (8 row-pairs)
    unsigned long long ag[8], av[8];
    float mg = 0.0f, mv = 0.0f;   // rank-1 center-local contribution (same for all rows)
    #pragma unroll
    for (int p = 0; p < 8; p++) { ag[p] = 0ULL; av[p] = 0ULL; }

    const float* wg_c = Wg + t;
    const float* wv_c = Wv + t;

    // block A: pair features (weight rows 0..127)
    #pragma unroll 2
    for (int k = 0; k < 128; k++) {
        float wgv = __ldg(wg_c + k * HH);
        float wvv = __ldg(wv_c + k * HH);
        unsigned long long bgp = pack2(wgv, wgv);
        unsigned long long bvp = pack2(wvv, wvv);
        const unsigned long long* xr = reinterpret_cast<const unsigned long long*>(xs + k * 16);
        #pragma unroll
        for (int p = 0; p < 8; p++) {
            unsigned long long a = xr[p];
            fma2(ag[p], a, bgp);
            fma2(av[p], a, bvp);
        }
    }
    // block B: center local (weight rows 128..255) — rank-1, compute once
    #pragma unroll 4
    for (int k = 0; k < 128; k++) {
        float lv = lvec[k];
        mg = fmaf(lv, __ldg(wg_c + (128 + k) * HH), mg);
        mv = fmaf(lv, __ldg(wv_c + (128 + k) * HH), mv);
    }
    // block C: neighbour local (weight rows 256..383, xs rows 128..255)
    #pragma unroll 2
    for (int k = 0; k < 128; k++) {
        float wgv = __ldg(wg_c + (256 + k) * HH);
        float wvv = __ldg(wv_c + (256 + k) * HH);
        unsigned long long bgp = pack2(wgv, wgv);
        unsigned long long bvp = pack2(wvv, wvv);
        const unsigned long long* xr = reinterpret_cast<const unsigned long long*>(xs + (128 + k) * 16);
        #pragma unroll
        for (int p = 0; p < 8; p++) {
            unsigned long long a = xr[p];
            fma2(ag[p], a, bgp);
            fma2(av[p], a, bvp);
        }
    }

    // epilogue: h = gelu(g) * v, transpose-store to hs[c*16 + r]
    {
        float bgc = bg[t] + mg;
        float bvc = bv[t] + mv;
        #pragma unroll
        for (int p = 0; p < 8; p++) {
            float g0, g1, v0, v1;
            unpack2(ag[p], g0, g1);
            unpack2(av[p], v0, v1);
            hs[t * 16 + 2 * p]     = gelu_tanh(g0 + bgc) * (v0 + bvc);
            hs[t * 16 + 2 * p + 1] = gelu_tanh(g1 + bgc) * (v1 + bvc);
        }
    }
    __syncthreads();

    // ---------------- GEMM2: u = h @ Wo + bo -----------------
    const int c  = t & (DD - 1);
    const int rh = t >> 7;   // row half: rows rh*8 .. rh*8+7
    {
        unsigned long long au[4];
        #pragma unroll
        for (int p = 0; p < 4; p++) au[p] = 0ULL;
        const float* wo_c = Wo + c;
        #pragma unroll 2
        for (int k = 0; k < HH; k++) {
            float w = __ldg(wo_c + k * DD);
            unsigned long long bw = pack2(w, w);
            const unsigned long long* hr =
                reinterpret_cast<const unsigned long long*>(hs + k * 16) + rh * 4;
            #pragma unroll
            for (int p = 0; p < 4; p++) fma2(au[p], hr[p], bw);
        }
        float boc = bo[c];
        #pragma unroll
        for (int p = 0; p < 4; p++) {
            float u0, u1;
            unpack2(au[p], u0, u1);
            int r = rh * 8 + 2 * p;
            us[r * DD + c]       = u0 + boc;
            us[(r + 1) * DD + c] = u1 + boc;
        }
    }

    // ---------------- gates: sigmoid(pair @ Win/Wout) -----------------
    float si[8], so[8];
    {
        unsigned long long ai[4], aq[4];
        #pragma unroll
        for (int p = 0; p < 4; p++) { ai[p] = 0ULL; aq[p] = 0ULL; }
        const float* wi_c = Win + c;
        const float* wq_c = Wou + c;
        #pragma unroll 2
        for (int k = 0; k < DD; k++) {
            float wi = __ldg(wi_c + k * DD);
            float wq = __ldg(wq_c + k * DD);
            unsigned long long bi = pack2(wi, wi);
            unsigned long long bq = pack2(wq, wq);
            const unsigned long long* xr =
                reinterpret_cast<const unsigned long long*>(xs + k * 16) + rh * 4;
            #pragma unroll
            for (int p = 0; p < 4; p++) {
                unsigned long long a = xr[p];
                fma2(ai[p], a, bi);
                fma2(aq[p], a, bq);
            }
        }
        #pragma unroll
        for (int p = 0; p < 4; p++) {
            float a0, a1, b0, b1;
            unpack2(ai[p], a0, a1);
            unpack2(aq[p], b0, b1);
            si[2 * p] = sigm(a0); si[2 * p + 1] = sigm(a1);
            so[2 * p] = sigm(b0); so[2 * p + 1] = sigm(b1);
        }
    }
    __syncthreads();

    // ---------------- LayerNorm (per row), pu in-place, pair_out -----------------
    {
        int wid = t >> 5, lane = t & 31;
        #pragma unroll
        for (int rr = 0; rr < 2; rr++) {
            int r = wid * 2 + rr;
            float v0 = us[r * DD + lane];
            float v1 = us[r * DD + lane + 32];
            float v2 = us[r * DD + lane + 64];
            float v3 = us[r * DD + lane + 96];
            float s  = v0 + v1 + v2 + v3;
            float sq = v0 * v0 + v1 * v1 + v2 * v2 + v3 * v3;
            #pragma unroll
            for (int o = 16; o > 0; o >>= 1) {
                s  += __shfl_xor_sync(0xffffffffu, s, o);
                sq += __shfl_xor_sync(0xffffffffu, sq, o);
            }
            float m    = s * (1.0f / 128.0f);
            float var  = sq * (1.0f / 128.0f) - m * m;
            float rstd = rsqrtf(var + 1e-5f);
            #pragma unroll
            for (int j = 0; j < 4; j++) {
                int col = lane + j * 32;
                float u  = us[r * DD + col];
                float pu = (u - m) * rstd * gp[col] + bp[col];
                us[r * DD + col] = pu;
                out[NN * DD + (n * KK + r) * DD + col] =
                    pair[(n * KK + r) * DD + col] + pu;
            }
        }
    }
    __syncthreads();

    // ---------------- incoming (CTA-local) + outgoing (atomic scatter) ----------
    {
        float* part = hs;   // hs is dead now — reuse as [2][128] partials
        float acc = 0.0f;
        #pragma unroll
        for (int p = 0; p < 8; p++) {
            int r = rh * 8 + p;
            float vm = svalid[r];
            float pu = us[r * DD + c];
            acc += vm * si[p] * pu;
            if (vm > 0.0f) {
                atomicAdd(&g_outgoing[snbr[r] * DD + c], so[p] * pu);
            }
        }
        part[rh * DD + c] = acc;
        __syncthreads();
        if (t < DD) g_incoming[n * DD + t] = part[t] + part[DD + t];
    }
}

// ---------------------------------------------------------------
// Local kernel: 1 CTA (256 threads) per 16 nodes
// ---------------------------------------------------------------
__global__ void __launch_bounds__(256, 2) local_kernel(
    const float* __restrict__ local,
    const float* __restrict__ Wg, const float* __restrict__ bg,
    const float* __restrict__ Wv, const float* __restrict__ bv,
    const float* __restrict__ Wo, const float* __restrict__ bo,
    const float* __restrict__ gl, const float* __restrict__ bl,
    float* __restrict__ out)
{
    __shared__ __align__(16) float buf[384 * 16 + 256 * 16];  // 40 KB
    float* xs = buf;              // 384 k-rows x 16 nodes
    float* hs = buf + 384 * 16;   // 256 x 16
    float* us = buf;              // alias xs (xs dead after GEMM1)

    const int t = threadIdx.x;
    const int base = blockIdx.x * KK;

    for (int i = t; i < FF * 16; i += 256) {
        int k = i % FF;
        int r = i / FF;
        int node = base + r;
        float v;
        if (k < DD)            v = local[node * DD + k];
        else if (k < 2 * DD)   v = g_incoming[node * DD + (k - DD)];
        else                   v = g_outgoing[node * DD + (k - 2 * DD)];
        xs[k * 16 + r] = v;
    }
    __syncthreads();

    // GEMM1: full 384-feature loop (all blocks per-row distinct)
    unsigned long long ag[8], av[8];
    #pragma unroll
    for (int p = 0; p < 8; p++) { ag[p] = 0ULL; av[p] = 0ULL; }
    {
        const float* wg_c = Wg + t;
        const float* wv_c = Wv + t;
        #pragma unroll 2
        for (int k = 0; k < FF; k++) {
            float wgv = __ldg(wg_c + k * HH);
            float wvv = __ldg(wv_c + k * HH);
            unsigned long long bgp = pack2(wgv, wgv);
            unsigned long long bvp = pack2(wvv, wvv);
            const unsigned long long* xr =
                reinterpret_cast<const unsigned long long*>(xs + k * 16);
            #pragma unroll
            for (int p = 0; p < 8; p++) {
                unsigned long long a = xr[p];
                fma2(ag[p], a, bgp);
                fma2(av[p], a, bvp);
            }
        }
    }
    {
        float bgc = bg[t], bvc = bv[t];
        #pragma unroll
        for (int p = 0; p < 8; p++) {
            float g0, g1, v0, v1;
            unpack2(ag[p], g0, g1);
            unpack2(av[p], v0, v1);
            hs[t * 16 + 2 * p]     = gelu_tanh(g0 + bgc) * (v0 + bvc);
            hs[t * 16 + 2 * p + 1] = gelu_tanh(g1 + bgc) * (v1 + bvc);
        }
    }
    __syncthreads();

    // GEMM2 -> us (aliases xs, which is dead)
    const int c  = t & (DD - 1);
    const int rh = t >> 7;
    {
        unsigned long long au[4];
        #pragma unroll
        for (int p = 0; p < 4; p++) au[p] = 0ULL;
        const float* wo_c = Wo + c;
        #pragma unroll 2
        for (int k = 0; k < HH; k++) {
            float w = __ldg(wo_c + k * DD);
            unsigned long long bw = pack2(w, w);
            const unsigned long long* hr =
                reinterpret_cast<const unsigned long long*>(hs + k * 16) + rh * 4;
            #pragma unroll
            for (int p = 0; p < 4; p++) fma2(au[p], hr[p], bw);
        }
        float boc = bo[c];
        #pragma unroll
        for (int p = 0; p < 4; p++) {
            float u0, u1;
            unpack2(au[p], u0, u1);
            int r = rh * 8 + 2 * p;
            us[r * DD + c]       = u0 + boc;
            us[(r + 1) * DD + c] = u1 + boc;
        }
    }
    __syncthreads();

    // LayerNorm + residual write
    {
        int wid = t >> 5, lane = t & 31;
        #pragma unroll
        for (int rr = 0; rr < 2; rr++) {
            int r = wid * 2 + rr;
            float v0 = us[r * DD + lane];
            float v1 = us[r * DD + lane + 32];
            float v2 = us[r * DD + lane + 64];
            float v3 = us[r * DD + lane + 96];
            float s  = v0 + v1 + v2 + v3;
            float sq = v0 * v0 + v1 * v1 + v2 * v2 + v3 * v3;
            #pragma unroll
            for (int o = 16; o > 0; o >>= 1) {
                s  += __shfl_xor_sync(0xffffffffu, s, o);
                sq += __shfl_xor_sync(0xffffffffu, sq, o);
            }
            float m    = s * (1.0f / 128.0f);
            float var  = sq * (1.0f / 128.0f) - m * m;
            float rstd = rsqrtf(var + 1e-5f);
            int node = base + r;
            #pragma unroll
            for (int j = 0; j < 4; j++) {
                int col = lane + j * 32;
                float u  = us[r * DD + col];
                float lu = (u - m) * rstd * gl[col] + bl[col];
                out[node * DD + col] = local[node * DD + col] + lu;
            }
        }
    }
}

// ---------------------------------------------------------------
extern "C" void kernel_launch(void* const* d_in, const int* in_sizes, int n_in,
                              void* d_out, int out_size)
{
    const float* local = (const float*)d_in[0];
    const float* pair  = (const float*)d_in[1];
    const int*   nbrs  = (const int*)  d_in[2];
    const float* mask  = (const float*)d_in[3];
    const float* Wg1 = (const float*)d_in[4];
    const float* bg1 = (const float*)d_in[5];
    const float* Wv1 = (const float*)d_in[6];
    const float* bv1 = (const float*)d_in[7];
    const float* Wo1 = (const float*)d_in[8];
    const float* bo1 = (const float*)d_in[9];
    const float* gp  = (const float*)d_in[10];
    const float* bp  = (const float*)d_in[11];
    const float* Win = (const float*)d_in[12];
    const float* Wou = (const float*)d_in[13];
    const float* Wg2 = (const float*)d_in[14];
    const float* bg2 = (const float*)d_in[15];
    const float* Wv2 = (const float*)d_in[16];
    const float* bv2 = (const float*)d_in[17];
    const float* Wo2 = (const float*)d_in[18];
    const float* bo2 = (const float*)d_in[19];
    const float* gl  = (const float*)d_in[20];
    const float* bl  = (const float*)d_in[21];
    float* out = (float*)d_out;

    zero_kernel<<<(NN * DD + 1023) / 1024, 1024>>>();
    pair_kernel<<<NN, 256>>>(local, pair, nbrs, mask,
                             Wg1, bg1, Wv1, bv1, Wo1, bo1, gp, bp, Win, Wou, out);
    local_kernel<<<NN / KK, 256>>>(local, Wg2, bg2, Wv2, bv2, Wo2, bo2, gl, bl, out);
}

// round 6
// speedup vs baseline: 1.0036x; 1.0036x over previous
#include <cuda_runtime.h>
#include <math.h>

#define NN 20000
#define KK 16
#define DD 128
#define HH 256
#define FF 384

// scratch (allocation-free rule: __device__ globals)
__device__ float g_incoming[NN * DD];
__device__ float g_outgoing[NN * DD];

// ---------- f32x2 helpers (sm_103a packed fp32 pipe) ----------
__device__ __forceinline__ unsigned long long pack2(float x, float y) {
    unsigned long long r;
    asm("mov.b64 %0, {%1, %2};" : "=l"(r) : "f"(x), "f"(y));
    return r;
}
__device__ __forceinline__ void unpack2(unsigned long long a, float& x, float& y) {
    asm("mov.b64 {%0, %1}, %2;" : "=f"(x), "=f"(y) : "l"(a));
}
__device__ __forceinline__ void fma2(unsigned long long& d, unsigned long long a, unsigned long long b) {
    asm("fma.rn.f32x2 %0, %1, %2, %0;" : "+l"(d) : "l"(a), "l"(b));
}

__device__ __forceinline__ float gelu_tanh(float x) {
    float x3 = x * x * x;
    return 0.5f * x * (1.0f + tanhf(0.7978845608028654f * (x + 0.044715f * x3)));
}
__device__ __forceinline__ float sigm(float x) {
    return 1.0f / (1.0f + expf(-x));
}

// ---------------------------------------------------------------
// zero the outgoing scatter buffer every launch (deterministic)
// ---------------------------------------------------------------
__global__ void zero_kernel() {
    int i = blockIdx.x * blockDim.x + threadIdx.x;
    if (i < NN * DD) g_outgoing[i] = 0.0f;
}

// ---------------------------------------------------------------
// Pair kernel: 1 CTA (256 threads) per node (16 neighbour rows)
// ---------------------------------------------------------------
__global__ void __launch_bounds__(256, 2) pair_kernel(
    const float* __restrict__ local, const float* __restrict__ pair,
    const int*   __restrict__ nbrs,  const float* __restrict__ mask,
    const float* __restrict__ Wg,  const float* __restrict__ bg,
    const float* __restrict__ Wv,  const float* __restrict__ bv,
    const float* __restrict__ Wo,  const float* __restrict__ bo,
    const float* __restrict__ gp,  const float* __restrict__ bp,
    const float* __restrict__ Win, const float* __restrict__ Wou,
    float* __restrict__ out)
{
    // xs: transposed per-row features, 256 k-rows x 16 rows (pair block + nbr block)
    __shared__ __align__(16) float xs[256 * 16];   // 16 KB
    __shared__ float lvec[128];                    // center local (shared across rows)
    __shared__ __align__(16) float hs[256 * 16];   // hidden, 16 KB
    __shared__ float us[16 * 128];                 // u, then pu in-place
    __shared__ int   snbr[16];
    __shared__ float svalid[16];

    const int t = threadIdx.x;
    const int n = blockIdx.x;

    if (t < KK) {
        int nb = nbrs[n * KK + t];
        snbr[t] = nb;
        svalid[t] = (nb != -1 && mask[nb < 0 ? nb + NN : nb] > 0.0f) ? 1.0f : 0.0f;
    }
    if (t >= 32 && t < 160) lvec[t - 32] = local[n * DD + (t - 32)];
    __syncthreads();

    // gather: k2<128 -> pair[n][r][k2]; k2>=128 -> local[nbr[r]][k2-128]
    for (int i = t; i < 256 * 16; i += 256) {
        int k2 = i & 255;
        int r  = i >> 8;
        float v;
        if (k2 < 128) {
            v = pair[(n * KK + r) * DD + k2];
        } else {
            int nb = snbr[r];
            if (nb < 0) nb += NN;           // mimic python negative-index wrap
            v = local[nb * DD + (k2 - 128)];
        }
        xs[k2 * 16 + r] = v;
    }
    __syncthreads();

    // ---------------- GEMM1: g/v hidden pre-activations -----------------
    // thread t owns hidden column c = t for all 16 rows (8 row-pairs)
    unsigned long long ag[8], av[8];
    float mg = 0.0f, mv = 0.0f;   // rank-1 center-local contribution (same for all rows)
    #pragma unroll
    for (int p = 0; p < 8; p++) { ag[p] = 0ULL; av[p] = 0ULL; }

    const float* wg_c = Wg + t;
    const float* wv_c = Wv + t;

    // block A: pair features (weight rows 0..127)
    #pragma unroll 2
    for (int k = 0; k < 128; k++) {
        float wgv = __ldg(wg_c + k * HH);
        float wvv = __ldg(wv_c + k * HH);
        unsigned long long bgp = pack2(wgv, wgv);
        unsigned long long bvp = pack2(wvv, wvv);
        const unsigned long long* xr = reinterpret_cast<const unsigned long long*>(xs + k * 16);
        #pragma unroll
        for (int p = 0; p < 8; p++) {
            unsigned long long a = xr[p];
            fma2(ag[p], a, bgp);
            fma2(av[p], a, bvp);
        }
    }
    // block B: center local (weight rows 128..255) — rank-1, compute once
    #pragma unroll 4
    for (int k = 0; k < 128; k++) {
        float lv = lvec[k];
        mg = fmaf(lv, __ldg(wg_c + (128 + k) * HH), mg);
        mv = fmaf(lv, __ldg(wv_c + (128 + k) * HH), mv);
    }
    // block C: neighbour local (weight rows 256..383, xs rows 128..255)
    #pragma unroll 2
    for (int k = 0; k < 128; k++) {
        float wgv = __ldg(wg_c + (256 + k) * HH);
        float wvv = __ldg(wv_c + (256 + k) * HH);
        unsigned long long bgp = pack2(wgv, wgv);
        unsigned long long bvp = pack2(wvv, wvv);
        const unsigned long long* xr = reinterpret_cast<const unsigned long long*>(xs + (128 + k) * 16);
        #pragma unroll
        for (int p = 0; p < 8; p++) {
            unsigned long long a = xr[p];
            fma2(ag[p], a, bgp);
            fma2(av[p], a, bvp);
        }
    }

    // epilogue: h = gelu(g) * v, transpose-store to hs[c*16 + r]
    {
        float bgc = bg[t] + mg;
        float bvc = bv[t] + mv;
        #pragma unroll
        for (int p = 0; p < 8; p++) {
            float g0, g1, v0, v1;
            unpack2(ag[p], g0, g1);
            unpack2(av[p], v0, v1);
            hs[t * 16 + 2 * p]     = gelu_tanh(g0 + bgc) * (v0 + bvc);
            hs[t * 16 + 2 * p + 1] = gelu_tanh(g1 + bgc) * (v1 + bvc);
        }
    }
    __syncthreads();

    // ---------------- GEMM2: u = h @ Wo + bo -----------------
    const int c  = t & (DD - 1);
    const int rh = t >> 7;   // row half: rows rh*8 .. rh*8+7
    {
        unsigned long long au[4];
        #pragma unroll
        for (int p = 0; p < 4; p++) au[p] = 0ULL;
        const float* wo_c = Wo + c;
        #pragma unroll 2
        for (int k = 0; k < HH; k++) {
            float w = __ldg(wo_c + k * DD);
            unsigned long long bw = pack2(w, w);
            const unsigned long long* hr =
                reinterpret_cast<const unsigned long long*>(hs + k * 16) + rh * 4;
            #pragma unroll
            for (int p = 0; p < 4; p++) fma2(au[p], hr[p], bw);
        }
        float boc = bo[c];
        #pragma unroll
        for (int p = 0; p < 4; p++) {
            float u0, u1;
            unpack2(au[p], u0, u1);
            int r = rh * 8 + 2 * p;
            us[r * DD + c]       = u0 + boc;
            us[(r + 1) * DD + c] = u1 + boc;
        }
    }

    // ---------------- gates: sigmoid(pair @ Win/Wout) -----------------
    float si[8], so[8];
    {
        unsigned long long ai[4], aq[4];
        #pragma unroll
        for (int p = 0; p < 4; p++) { ai[p] = 0ULL; aq[p] = 0ULL; }
        const float* wi_c = Win + c;
        const float* wq_c = Wou + c;
        #pragma unroll 2
        for (int k = 0; k < DD; k++) {
            float wi = __ldg(wi_c + k * DD);
            float wq = __ldg(wq_c + k * DD);
            unsigned long long bi = pack2(wi, wi);
            unsigned long long bq = pack2(wq, wq);
            const unsigned long long* xr =
                reinterpret_cast<const unsigned long long*>(xs + k * 16) + rh * 4;
            #pragma unroll
            for (int p = 0; p < 4; p++) {
                unsigned long long a = xr[p];
                fma2(ai[p], a, bi);
                fma2(aq[p], a, bq);
            }
        }
        #pragma unroll
        for (int p = 0; p < 4; p++) {
            float a0, a1, b0, b1;
            unpack2(ai[p], a0, a1);
            unpack2(aq[p], b0, b1);
            si[2 * p] = sigm(a0); si[2 * p + 1] = sigm(a1);
            so[2 * p] = sigm(b0); so[2 * p + 1] = sigm(b1);
        }
    }
    __syncthreads();

    // ---------------- LayerNorm (per row), pu in-place, pair_out -----------------
    {
        int wid = t >> 5, lane = t & 31;
        #pragma unroll
        for (int rr = 0; rr < 2; rr++) {
            int r = wid * 2 + rr;
            float v0 = us[r * DD + lane];
            float v1 = us[r * DD + lane + 32];
            float v2 = us[r * DD + lane + 64];
            float v3 = us[r * DD + lane + 96];
            float s  = v0 + v1 + v2 + v3;
            float sq = v0 * v0 + v1 * v1 + v2 * v2 + v3 * v3;
            #pragma unroll
            for (int o = 16; o > 0; o >>= 1) {
                s  += __shfl_xor_sync(0xffffffffu, s, o);
                sq += __shfl_xor_sync(0xffffffffu, sq, o);
            }
            float m    = s * (1.0f / 128.0f);
            float var  = sq * (1.0f / 128.0f) - m * m;
            float rstd = rsqrtf(var + 1e-5f);
            #pragma unroll
            for (int j = 0; j < 4; j++) {
                int col = lane + j * 32;
                float u  = us[r * DD + col];
                float pu = (u - m) * rstd * gp[col] + bp[col];
                us[r * DD + col] = pu;
                out[NN * DD + (n * KK + r) * DD + col] =
                    pair[(n * KK + r) * DD + col] + pu;
            }
        }
    }
    __syncthreads();

    // ---------------- incoming (CTA-local) + outgoing (atomic scatter) ----------
    {
        float* part = hs;   // hs is dead now — reuse as [2][128] partials
        float acc = 0.0f;
        #pragma unroll
        for (int p = 0; p < 8; p++) {
            int r = rh * 8 + p;
            float vm = svalid[r];
            float pu = us[r * DD + c];
            acc += vm * si[p] * pu;
            if (vm > 0.0f) {
                atomicAdd(&g_outgoing[snbr[r] * DD + c], so[p] * pu);
            }
        }
        part[rh * DD + c] = acc;
        __syncthreads();
        if (t < DD) g_incoming[n * DD + t] = part[t] + part[DD + t];
    }
}

// ---------------------------------------------------------------
// Local kernel: 1 CTA (256 threads) per 16 nodes
// ---------------------------------------------------------------
__global__ void __launch_bounds__(256, 2) local_kernel(
    const float* __restrict__ local,
    const float* __restrict__ Wg, const float* __restrict__ bg,
    const float* __restrict__ Wv, const float* __restrict__ bv,
    const float* __restrict__ Wo, const float* __restrict__ bo,
    const float* __restrict__ gl, const float* __restrict__ bl,
    float* __restrict__ out)
{
    __shared__ __align__(16) float buf[384 * 16 + 256 * 16];  // 40 KB
    float* xs = buf;              // 384 k-rows x 16 nodes
    float* hs = buf + 384 * 16;   // 256 x 16
    float* us = buf;              // alias xs (xs dead after GEMM1)

    const int t = threadIdx.x;
    const int base = blockIdx.x * KK;

    for (int i = t; i < FF * 16; i += 256) {
        int k = i % FF;
        int r = i / FF;
        int node = base + r;
        float v;
        if (k < DD)            v = local[node * DD + k];
        else if (k < 2 * DD)   v = g_incoming[node * DD + (k - DD)];
        else                   v = g_outgoing[node * DD + (k - 2 * DD)];
        xs[k * 16 + r] = v;
    }
    __syncthreads();

    // GEMM1: full 384-feature loop (all blocks per-row distinct)
    unsigned long long ag[8], av[8];
    #pragma unroll
    for (int p = 0; p < 8; p++) { ag[p] = 0ULL; av[p] = 0ULL; }
    {
        const float* wg_c = Wg + t;
        const float* wv_c = Wv + t;
        #pragma unroll 2
        for (int k = 0; k < FF; k++) {
            float wgv = __ldg(wg_c + k * HH);
            float wvv = __ldg(wv_c + k * HH);
            unsigned long long bgp = pack2(wgv, wgv);
            unsigned long long bvp = pack2(wvv, wvv);
            const unsigned long long* xr =
                reinterpret_cast<const unsigned long long*>(xs + k * 16);
            #pragma unroll
            for (int p = 0; p < 8; p++) {
                unsigned long long a = xr[p];
                fma2(ag[p], a, bgp);
                fma2(av[p], a, bvp);
            }
        }
    }
    {
        float bgc = bg[t], bvc = bv[t];
        #pragma unroll
        for (int p = 0; p < 8; p++) {
            float g0, g1, v0, v1;
            unpack2(ag[p], g0, g1);
            unpack2(av[p], v0, v1);
            hs[t * 16 + 2 * p]     = gelu_tanh(g0 + bgc) * (v0 + bvc);
            hs[t * 16 + 2 * p + 1] = gelu_tanh(g1 + bgc) * (v1 + bvc);
        }
    }
    __syncthreads();

    // GEMM2 -> us (aliases xs, which is dead)
    const int c  = t & (DD - 1);
    const int rh = t >> 7;
    {
        unsigned long long au[4];
        #pragma unroll
        for (int p = 0; p < 4; p++) au[p] = 0ULL;
        const float* wo_c = Wo + c;
        #pragma unroll 2
        for (int k = 0; k < HH; k++) {
            float w = __ldg(wo_c + k * DD);
            unsigned long long bw = pack2(w, w);
            const unsigned long long* hr =
                reinterpret_cast<const unsigned long long*>(hs + k * 16) + rh * 4;
            #pragma unroll
            for (int p = 0; p < 4; p++) fma2(au[p], hr[p], bw);
        }
        float boc = bo[c];
        #pragma unroll
        for (int p = 0; p < 4; p++) {
            float u0, u1;
            unpack2(au[p], u0, u1);
            int r = rh * 8 + 2 * p;
            us[r * DD + c]       = u0 + boc;
            us[(r + 1) * DD + c] = u1 + boc;
        }
    }
    __syncthreads();

    // LayerNorm + residual write
    {
        int wid = t >> 5, lane = t & 31;
        #pragma unroll
        for (int rr = 0; rr < 2; rr++) {
            int r = wid * 2 + rr;
            float v0 = us[r * DD + lane];
            float v1 = us[r * DD + lane + 32];
            float v2 = us[r * DD + lane + 64];
            float v3 = us[r * DD + lane + 96];
            float s  = v0 + v1 + v2 + v3;
            float sq = v0 * v0 + v1 * v1 + v2 * v2 + v3 * v3;
            #pragma unroll
            for (int o = 16; o > 0; o >>= 1) {
                s  += __shfl_xor_sync(0xffffffffu, s, o);
                sq += __shfl_xor_sync(0xffffffffu, sq, o);
            }
            float m    = s * (1.0f / 128.0f);
            float var  = sq * (1.0f / 128.0f) - m * m;
            float rstd = rsqrtf(var + 1e-5f);
            int node = base + r;
            #pragma unroll
            for (int j = 0; j < 4; j++) {
                int col = lane + j * 32;
                float u  = us[r * DD + col];
                float lu = (u - m) * rstd * gl[col] + bl[col];
                out[node * DD + col] = local[node * DD + col] + lu;
            }
        }
    }
}

// ---------------------------------------------------------------
extern "C" void kernel_launch(void* const* d_in, const int* in_sizes, int n_in,
                              void* d_out, int out_size)
{
    const float* local = (const float*)d_in[0];
    const float* pair  = (const float*)d_in[1];
    const int*   nbrs  = (const int*)  d_in[2];
    const float* mask  = (const float*)d_in[3];
    const float* Wg1 = (const float*)d_in[4];
    const float* bg1 = (const float*)d_in[5];
    const float* Wv1 = (const float*)d_in[6];
    const float* bv1 = (const float*)d_in[7];
    const float* Wo1 = (const float*)d_in[8];
    const float* bo1 = (const float*)d_in[9];
    const float* gp  = (const float*)d_in[10];
    const float* bp  = (const float*)d_in[11];
    const float* Win = (const float*)d_in[12];
    const float* Wou = (const float*)d_in[13];
    const float* Wg2 = (const float*)d_in[14];
    const float* bg2 = (const float*)d_in[15];
    const float* Wv2 = (const float*)d_in[16];
    const float* bv2 = (const float*)d_in[17];
    const float* Wo2 = (const float*)d_in[18];
    const float* bo2 = (const float*)d_in[19];
    const float* gl  = (const float*)d_in[20];
    const float* bl  = (const float*)d_in[21];
    float* out = (float*)d_out;

    zero_kernel<<<(NN * DD + 1023) / 1024, 1024>>>();
    pair_kernel<<<NN, 256>>>(local, pair, nbrs, mask,
                             Wg1, bg1, Wv1, bv1, Wo1, bo1, gp, bp, Win, Wou, out);
    local_kernel<<<NN / KK, 256>>>(local, Wg2, bg2, Wv2, bv2, Wo2, bo2, gl, bl, out);
}

// round 10
// speedup vs baseline: 2.1111x; 2.1035x over previous
#include <cuda_runtime.h>
#include <cuda_bf16.h>
#include <cstdint>
#include <math.h>

#define NNODES 20000
#define KNBR 16
#define DDIM 128
#define NR (NNODES * KNBR)   /* 320000 pair rows */

// ======================= device scratch (allocation-free) =======================
__device__ __nv_bfloat16 g_A1h[(size_t)NR * 256];
__device__ __nv_bfloat16 g_A1l[(size_t)NR * 256];
__device__ float         g_big[(size_t)NR * 512];   // Hpre; later S gates (first NR*256) + u_pre tail
__device__ __nv_bfloat16 g_Hh[(size_t)NR * 256];
__device__ __nv_bfloat16 g_Hl[(size_t)NR * 256];
__device__ float         g_pu[(size_t)NR * 128];
__device__ float         g_Cc[(size_t)NNODES * 512];  // Cc; later H2pre
__device__ float         g_inc[NNODES * DDIM];
__device__ float         g_outg[NNODES * DDIM];
__device__ __nv_bfloat16 g_Lh[NNODES * DDIM], g_Ll[NNODES * DDIM];
__device__ __nv_bfloat16 g_X2h[NNODES * 384], g_X2l[NNODES * 384];
__device__ __nv_bfloat16 g_X3h[(size_t)NNODES * 256], g_X3l[(size_t)NNODES * 256];
// weights, split bf16, stored [n][k] (K-major rows)
__device__ __nv_bfloat16 gW13h[512 * 256], gW13l[512 * 256];
__device__ __nv_bfloat16 gWch[512 * 128],  gWcl[512 * 128];
__device__ __nv_bfloat16 gBo1h[128 * 256], gBo1l[128 * 256];
__device__ __nv_bfloat16 gBioh[256 * 128], gBiol[256 * 128];
__device__ __nv_bfloat16 gB2h[512 * 384],  gB2l[512 * 384];
__device__ __nv_bfloat16 gBo2h[128 * 256], gBo2l[128 * 256];

#define UPRE (g_big + (size_t)NR * 256)

// ======================= math helpers =======================
__device__ __forceinline__ float gelu_tanh(float x) {
    float x3 = x * x * x;
    return 0.5f * x * (1.0f + tanhf(0.7978845608028654f * (x + 0.044715f * x3)));
}
__device__ __forceinline__ float sigm(float x) { return 1.0f / (1.0f + expf(-x)); }
__device__ __forceinline__ void split_bf16(float v, __nv_bfloat16& h, __nv_bfloat16& l) {
    h = __float2bfloat16(v);
    l = __float2bfloat16(v - __bfloat162float(h));
}

// ======================= mma.sync helper (sm_80+ PTX, HMMA on Blackwell) ========
__device__ __forceinline__ void mma16816(float* c, const uint32_t* a, uint32_t b0, uint32_t b1) {
    asm volatile(
        "mma.sync.aligned.m16n8k16.row.col.f32.bf16.bf16.f32 "
        "{%0,%1,%2,%3}, {%4,%5,%6,%7}, {%8,%9}, {%0,%1,%2,%3};"
        : "+f"(c[0]), "+f"(c[1]), "+f"(c[2]), "+f"(c[3])
        : "r"(a[0]), "r"(a[1]), "r"(a[2]), "r"(a[3]), "r"(b0), "r"(b1));
}

// ======================= split-bf16 GEMM via mma.sync =======================
// C[m0:m0+128, n0:n0+128] = (Ah+Al)[M,K] @ (Bh+Bl)[N,K]^T  (B K-major rows)
// 3-term split: AhBh + AhBl + AlBh.  8 warps: 4(m) x 2(n), warp tile 32x64.
#define SAS 20   /* padded row stride in uint32 (conflict-free fragment LDS) */

__global__ void __launch_bounds__(256)
gemm_kernel(const __nv_bfloat16* __restrict__ Ah, const __nv_bfloat16* __restrict__ Al,
            int lda, int M, int K,
            const __nv_bfloat16* __restrict__ Bh, const __nv_bfloat16* __restrict__ Bl,
            float* __restrict__ C, int ldc)
{
    __shared__ uint32_t sAh[128 * SAS], sAl[128 * SAS];
    __shared__ uint32_t sBh[128 * SAS], sBl[128 * SAS];

    const int t   = threadIdx.x;
    const int wid = t >> 5, lane = t & 31;
    const int lr  = lane >> 2, lc = lane & 3;
    const int wm  = wid & 3;          // 0..3  -> m offset 32*wm
    const int wn  = wid >> 2;         // 0..1  -> n offset 64*wn
    const int m0  = blockIdx.x * 128;
    const int n0  = blockIdx.y * 128;

    float acc[2][8][4];
    #pragma unroll
    for (int mf = 0; mf < 2; mf++)
        #pragma unroll
        for (int nf = 0; nf < 8; nf++)
            #pragma unroll
            for (int q = 0; q < 4; q++) acc[mf][nf][q] = 0.0f;

    const int nchunks = K >> 5;   // 32-wide K chunks
    for (int kc = 0; kc < nchunks; kc++) {
        // ---- load A: 2 planes x 128 rows x 4 uint4 (32 bf16/row) ----
        #pragma unroll
        for (int i = t; i < 1024; i += 256) {
            int p = i >> 9;
            int e = i & 511;
            int r = e >> 2, q = e & 3;
            int row = m0 + r;
            uint4 v = make_uint4(0u, 0u, 0u, 0u);
            if (row < M)
                v = *reinterpret_cast<const uint4*>(
                        (p ? Al : Ah) + (size_t)row * lda + kc * 32 + q * 8);
            uint32_t* dst = (p ? sAl : sAh) + r * SAS + q * 4;
            dst[0] = v.x; dst[1] = v.y; dst[2] = v.z; dst[3] = v.w;
        }
        // ---- load B: 2 planes x 128 n-rows x 4 uint4 ----
        #pragma unroll
        for (int i = t; i < 1024; i += 256) {
            int p = i >> 9;
            int e = i & 511;
            int r = e >> 2, q = e & 3;
            uint4 v = *reinterpret_cast<const uint4*>(
                          (p ? Bl : Bh) + (size_t)(n0 + r) * K + kc * 32 + q * 8);
            uint32_t* dst = (p ? sBl : sBh) + r * SAS + q * 4;
            dst[0] = v.x; dst[1] = v.y; dst[2] = v.z; dst[3] = v.w;
        }
        __syncthreads();

        #pragma unroll
        for (int s = 0; s < 2; s++) {   // two k16 steps per chunk
            const int kb = s * 8;       // uint32 offset in row
            // A fragments (both planes, 2 m-frags)
            uint32_t ah[2][4], al[2][4];
            #pragma unroll
            for (int mf = 0; mf < 2; mf++) {
                int rb = (wm * 32 + mf * 16 + lr) * SAS + kb + lc;
                int rb8 = rb + 8 * SAS;
                ah[mf][0] = sAh[rb];       ah[mf][1] = sAh[rb8];
                ah[mf][2] = sAh[rb + 4];   ah[mf][3] = sAh[rb8 + 4];
                al[mf][0] = sAl[rb];       al[mf][1] = sAl[rb8];
                al[mf][2] = sAl[rb + 4];   al[mf][3] = sAl[rb8 + 4];
            }
            #pragma unroll
            for (int nf = 0; nf < 8; nf++) {
                int cb = (wn * 64 + nf * 8 + lr) * SAS + kb + lc;
                uint32_t bh0 = sBh[cb], bh1 = sBh[cb + 4];
                uint32_t bl0 = sBl[cb], bl1 = sBl[cb + 4];
                #pragma unroll
                for (int mf = 0; mf < 2; mf++) {
                    mma16816(acc[mf][nf], ah[mf], bh0, bh1);
                    mma16816(acc[mf][nf], ah[mf], bl0, bl1);
                    mma16816(acc[mf][nf], al[mf], bh0, bh1);
                }
            }
        }
        __syncthreads();
    }

    // ---- epilogue: c0/c1 at (row, 2lc), c2/c3 at (row+8, 2lc) ----
    #pragma unroll
    for (int mf = 0; mf < 2; mf++) {
        int r0 = m0 + wm * 32 + mf * 16 + lr;
        int r1 = r0 + 8;
        #pragma unroll
        for (int nf = 0; nf < 8; nf++) {
            int col = n0 + wn * 64 + nf * 8 + 2 * lc;
            if (r0 < M)
                *reinterpret_cast<float2*>(C + (size_t)r0 * ldc + col) =
                    make_float2(acc[mf][nf][0], acc[mf][nf][1]);
            if (r1 < M)
                *reinterpret_cast<float2*>(C + (size_t)r1 * ldc + col) =
                    make_float2(acc[mf][nf][2], acc[mf][nf][3]);
        }
    }
}

// ======================= elementwise / prep kernels =======================
__global__ void zero_out_kernel() {
    int i = blockIdx.x * blockDim.x + threadIdx.x;
    if (i < NNODES * DDIM) g_outg[i] = 0.0f;
}

__global__ void prep_weights_kernel(
    const float* __restrict__ Wg1, const float* __restrict__ Wv1,
    const float* __restrict__ Wo1, const float* __restrict__ Win,
    const float* __restrict__ Wou, const float* __restrict__ Wg2,
    const float* __restrict__ Wv2, const float* __restrict__ Wo2)
{
    int i = blockIdx.x * blockDim.x + threadIdx.x;
    int stride = gridDim.x * blockDim.x;
    for (int x = i; x < 512 * 256; x += stride) {
        int n = x >> 8, k = x & 255;
        const float* W = (n < 256) ? Wg1 : Wv1;
        int krow = (k < 128) ? k : (256 + (k - 128));
        split_bf16(W[krow * 256 + (n & 255)], gW13h[x], gW13l[x]);
    }
    for (int x = i; x < 512 * 128; x += stride) {
        int n = x >> 7, k = x & 127;
        const float* W = (n < 256) ? Wg1 : Wv1;
        split_bf16(W[(128 + k) * 256 + (n & 255)], gWch[x], gWcl[x]);
    }
    for (int x = i; x < 128 * 256; x += stride) {
        int n = x >> 8, k = x & 255;
        split_bf16(Wo1[k * 128 + n], gBo1h[x], gBo1l[x]);
    }
    for (int x = i; x < 256 * 128; x += stride) {
        int n = x >> 7, k = x & 127;
        const float* W = (n < 128) ? Win : Wou;
        split_bf16(W[k * 128 + (n & 127)], gBioh[x], gBiol[x]);
    }
    for (int x = i; x < 512 * 384; x += stride) {
        int n = x / 384, k = x % 384;
        const float* W = (n < 256) ? Wg2 : Wv2;
        split_bf16(W[k * 256 + (n & 255)], gB2h[x], gB2l[x]);
    }
    for (int x = i; x < 128 * 256; x += stride) {
        int n = x >> 8, k = x & 255;
        split_bf16(Wo2[k * 128 + n], gBo2h[x], gBo2l[x]);
    }
}

__global__ void prep_A1_kernel(const float* __restrict__ pair, const float* __restrict__ local,
                               const int* __restrict__ nbrs)
{
    size_t i = (size_t)blockIdx.x * blockDim.x + threadIdx.x;
    if (i >= (size_t)NR * 256) return;
    int c = (int)(i & 255);
    size_t r = i >> 8;
    float v;
    if (c < 128) {
        v = pair[r * 128 + c];
    } else {
        int nb = nbrs[r];
        if (nb < 0) nb += NNODES;   // python wrap for -1
        v = local[(size_t)nb * 128 + (c - 128)];
    }
    split_bf16(v, g_A1h[i], g_A1l[i]);
}

__global__ void prep_L_kernel(const float* __restrict__ local) {
    int i = blockIdx.x * blockDim.x + threadIdx.x;
    if (i < NNODES * DDIM) split_bf16(local[i], g_Lh[i], g_Ll[i]);
}

__global__ void epi1_kernel(const float* __restrict__ bg, const float* __restrict__ bv) {
    size_t i = (size_t)blockIdx.x * blockDim.x + threadIdx.x;
    if (i >= (size_t)NR * 256) return;
    int c = (int)(i & 255);
    size_t r = i >> 8;
    size_t node = r >> 4;
    float g = g_big[r * 512 + c] + g_Cc[node * 512 + c] + bg[c];
    float v = g_big[r * 512 + 256 + c] + g_Cc[node * 512 + 256 + c] + bv[c];
    split_bf16(gelu_tanh(g) * v, g_Hh[i], g_Hl[i]);
}

__global__ void ln_pair_kernel(const float* __restrict__ pair, const float* __restrict__ bo,
                               const float* __restrict__ gp, const float* __restrict__ bp,
                               float* __restrict__ out)
{
    int row = blockIdx.x * 8 + (threadIdx.x >> 5);
    int lane = threadIdx.x & 31;
    if (row >= NR) return;
    const float* up = UPRE + (size_t)row * 128;
    float v[4], s = 0.0f, sq = 0.0f;
    #pragma unroll
    for (int j = 0; j < 4; j++) {
        int col = lane + j * 32;
        v[j] = up[col] + bo[col];
        s += v[j]; sq += v[j] * v[j];
    }
    #pragma unroll
    for (int o = 16; o > 0; o >>= 1) {
        s  += __shfl_xor_sync(0xffffffffu, s, o);
        sq += __shfl_xor_sync(0xffffffffu, sq, o);
    }
    float m = s * (1.0f / 128.0f);
    float var = sq * (1.0f / 128.0f) - m * m;
    float rstd = rsqrtf(var + 1e-5f);
    #pragma unroll
    for (int j = 0; j < 4; j++) {
        int col = lane + j * 32;
        float pu = (v[j] - m) * rstd * gp[col] + bp[col];
        g_pu[(size_t)row * 128 + col] = pu;
        out[(size_t)NNODES * 128 + (size_t)row * 128 + col] = pair[(size_t)row * 128 + col] + pu;
    }
}

__global__ void messages_kernel(const int* __restrict__ nbrs, const float* __restrict__ mask) {
    int n = blockIdx.x;
    int c = threadIdx.x;   // 128 threads
    float inc = 0.0f;
    #pragma unroll
    for (int kk = 0; kk < KNBR; kk++) {
        int row = n * KNBR + kk;
        int nb = nbrs[row];
        int nbw = (nb < 0) ? nb + NNODES : nb;
        bool valid = (nb != -1) && (mask[nbw] > 0.0f);
        if (valid) {
            float p  = g_pu[(size_t)row * 128 + c];
            float si = sigm(g_big[(size_t)row * 256 + c]);
            float so = sigm(g_big[(size_t)row * 256 + 128 + c]);
            inc += si * p;
            atomicAdd(&g_outg[nbw * 128 + c], so * p);
        }
    }
    g_inc[n * 128 + c] = inc;
}

__global__ void prep_X2_kernel(const float* __restrict__ local) {
    int i = blockIdx.x * blockDim.x + threadIdx.x;
    if (i >= NNODES * 384) return;
    int k = i % 384;
    int r = i / 384;
    float v;
    if (k < 128)       v = local[(size_t)r * 128 + k];
    else if (k < 256)  v = g_inc[r * 128 + (k - 128)];
    else               v = g_outg[r * 128 + (k - 256)];
    split_bf16(v, g_X2h[i], g_X2l[i]);
}

__global__ void epi2_kernel(const float* __restrict__ bg, const float* __restrict__ bv) {
    size_t i = (size_t)blockIdx.x * blockDim.x + threadIdx.x;
    if (i >= (size_t)NNODES * 256) return;
    int c = (int)(i & 255);
    size_t r = i >> 8;
    float g = g_Cc[r * 512 + c] + bg[c];
    float v = g_Cc[r * 512 + 256 + c] + bv[c];
    split_bf16(gelu_tanh(g) * v, g_X3h[i], g_X3l[i]);
}

__global__ void ln_local_kernel(const float* __restrict__ local, const float* __restrict__ bo,
                                const float* __restrict__ gl, const float* __restrict__ bl,
                                float* __restrict__ out)
{
    int row = blockIdx.x * 8 + (threadIdx.x >> 5);
    int lane = threadIdx.x & 31;
    if (row >= NNODES) return;
    const float* up = UPRE + (size_t)row * 128;
    float v[4], s = 0.0f, sq = 0.0f;
    #pragma unroll
    for (int j = 0; j < 4; j++) {
        int col = lane + j * 32;
        v[j] = up[col] + bo[col];
        s += v[j]; sq += v[j] * v[j];
    }
    #pragma unroll
    for (int o = 16; o > 0; o >>= 1) {
        s  += __shfl_xor_sync(0xffffffffu, s, o);
        sq += __shfl_xor_sync(0xffffffffu, sq, o);
    }
    float m = s * (1.0f / 128.0f);
    float var = sq * (1.0f / 128.0f) - m * m;
    float rstd = rsqrtf(var + 1e-5f);
    #pragma unroll
    for (int j = 0; j < 4; j++) {
        int col = lane + j * 32;
        float lu = (v[j] - m) * rstd * gl[col] + bl[col];
        out[(size_t)row * 128 + col] = local[(size_t)row * 128 + col] + lu;
    }
}

// ======================= launch =======================
extern "C" void kernel_launch(void* const* d_in, const int* in_sizes, int n_in,
                              void* d_out, int out_size)
{
    const float* local = (const float*)d_in[0];
    const float* pair  = (const float*)d_in[1];
    const int*   nbrs  = (const int*)  d_in[2];
    const float* mask  = (const float*)d_in[3];
    const float* Wg1 = (const float*)d_in[4];
    const float* bg1 = (const float*)d_in[5];
    const float* Wv1 = (const float*)d_in[6];
    const float* bv1 = (const float*)d_in[7];
    const float* Wo1 = (const float*)d_in[8];
    const float* bo1 = (const float*)d_in[9];
    const float* gp  = (const float*)d_in[10];
    const float* bp  = (const float*)d_in[11];
    const float* Win = (const float*)d_in[12];
    const float* Wou = (const float*)d_in[13];
    const float* Wg2 = (const float*)d_in[14];
    const float* bg2 = (const float*)d_in[15];
    const float* Wv2 = (const float*)d_in[16];
    const float* bv2 = (const float*)d_in[17];
    const float* Wo2 = (const float*)d_in[18];
    const float* bo2 = (const float*)d_in[19];
    const float* gl  = (const float*)d_in[20];
    const float* bl  = (const float*)d_in[21];
    float* out = (float*)d_out;

    float *gbig, *gcc;
    cudaGetSymbolAddress((void**)&gbig, g_big);
    cudaGetSymbolAddress((void**)&gcc,  g_Cc);
    __nv_bfloat16 *a1h, *a1l, *hh, *hl, *lh, *ll, *x2h, *x2l, *x3h, *x3l;
    cudaGetSymbolAddress((void**)&a1h, g_A1h); cudaGetSymbolAddress((void**)&a1l, g_A1l);
    cudaGetSymbolAddress((void**)&hh,  g_Hh);  cudaGetSymbolAddress((void**)&hl,  g_Hl);
    cudaGetSymbolAddress((void**)&lh,  g_Lh);  cudaGetSymbolAddress((void**)&ll,  g_Ll);
    cudaGetSymbolAddress((void**)&x2h, g_X2h); cudaGetSymbolAddress((void**)&x2l, g_X2l);
    cudaGetSymbolAddress((void**)&x3h, g_X3h); cudaGetSymbolAddress((void**)&x3l, g_X3l);
    __nv_bfloat16 *w13h, *w13l, *wch, *wcl, *bo1h, *bo1l, *bioh, *biol, *b2h, *b2l, *bo2h, *bo2l;
    cudaGetSymbolAddress((void**)&w13h, gW13h); cudaGetSymbolAddress((void**)&w13l, gW13l);
    cudaGetSymbolAddress((void**)&wch,  gWch);  cudaGetSymbolAddress((void**)&wcl,  gWcl);
    cudaGetSymbolAddress((void**)&bo1h, gBo1h); cudaGetSymbolAddress((void**)&bo1l, gBo1l);
    cudaGetSymbolAddress((void**)&bioh, gBioh); cudaGetSymbolAddress((void**)&biol, gBiol);
    cudaGetSymbolAddress((void**)&b2h,  gB2h);  cudaGetSymbolAddress((void**)&b2l,  gB2l);
    cudaGetSymbolAddress((void**)&bo2h, gBo2h); cudaGetSymbolAddress((void**)&bo2l, gBo2l);
    float* upre = gbig + (size_t)NR * 256;

    // 1) prep
    zero_out_kernel<<<(NNODES * DDIM + 255) / 256, 256>>>();
    prep_weights_kernel<<<512, 256>>>(Wg1, Wv1, Wo1, Win, Wou, Wg2, Wv2, Wo2);
    prep_A1_kernel<<<(int)(((size_t)NR * 256 + 255) / 256), 256>>>(pair, local, nbrs);
    prep_L_kernel<<<(NNODES * DDIM + 255) / 256, 256>>>(local);

    // 2) Cc = local @ Wcen : [20000,128]x[128,512]
    gemm_kernel<<<dim3(157, 4), 256>>>(lh, ll, 128, NNODES, 128, wch, wcl, gcc, 512);
    // 3) Hpre = A1 @ W13 : [320000,256]x[256,512]
    gemm_kernel<<<dim3(2500, 4), 256>>>(a1h, a1l, 256, NR, 256, w13h, w13l, gbig, 512);
    // 4) H = gelu(g)*v  (adds Cc + biases)
    epi1_kernel<<<(int)(((size_t)NR * 256 + 255) / 256), 256>>>(bg1, bv1);
    // 5) u_pre = H @ Wo1 : [320000,256]x[256,128] -> UPRE
    gemm_kernel<<<dim3(2500, 1), 256>>>(hh, hl, 256, NR, 256, bo1h, bo1l, upre, 128);
    // 6) gates S = A1.pair @ [Win||Wout] : [320000,128]x[128,256] (pair cols = A1 cols 0..127)
    gemm_kernel<<<dim3(2500, 2), 256>>>(a1h, a1l, 256, NR, 128, bioh, biol, gbig, 256);
    // 7) LN pair + residual pair output + store pu
    ln_pair_kernel<<<(NR + 7) / 8, 256>>>(pair, bo1, gp, bp, out);
    // 8) incoming sum + outgoing atomic scatter
    messages_kernel<<<NNODES, 128>>>(nbrs, mask);
    // 9) local features
    prep_X2_kernel<<<(NNODES * 384 + 255) / 256, 256>>>(local);
    // 10) H2pre = X2 @ B2 : [20000,384]x[384,512] -> g_Cc (reuse)
    gemm_kernel<<<dim3(157, 4), 256>>>(x2h, x2l, 384, NNODES, 384, b2h, b2l, gcc, 512);
    // 11) X3 = gelu(g)*v
    epi2_kernel<<<(int)(((size_t)NNODES * 256 + 255) / 256), 256>>>(bg2, bv2);
    // 12) u2_pre = X3 @ Wo2 : [20000,256]x[256,128] -> UPRE (reuse)
    gemm_kernel<<<dim3(157, 1), 256>>>(x3h, x3l, 256, NNODES, 256, bo2h, bo2l, upre, 128);
    // 13) LN local + residual local output
    ln_local_kernel<<<(NNODES + 7) / 8, 256>>>(local, bo2, gl, bl, out);
}

// round 11
// speedup vs baseline: 2.9590x; 1.4016x over previous
#include <cuda_runtime.h>
#include <cuda_bf16.h>
#include <cstdint>
#include <math.h>

#define NNODES 20000
#define KNBR 16
#define DDIM 128
#define NR (NNODES * KNBR)   /* 320000 pair rows */
#define SAS 20               /* padded smem row stride in uint32 */
#define DSMEM 81920          /* 2 stages x 4 planes x 128 x SAS x 4B */

// ======================= device scratch (allocation-free) =======================
__device__ __nv_bfloat16 g_A1h[(size_t)NR * 256];
__device__ __nv_bfloat16 g_A1l[(size_t)NR * 256];
__device__ float         g_big[(size_t)NR * 384];   // S gates [0,NR*256) + u_pre tail [NR*256,NR*384)
__device__ __nv_bfloat16 g_Hh[(size_t)NR * 256];
__device__ __nv_bfloat16 g_Hl[(size_t)NR * 256];
__device__ float         g_pu[(size_t)NR * 128];
__device__ float         g_Cc[(size_t)NNODES * 512];  // interleaved (g,v) per node; reused for nothing else
__device__ float         g_inc[NNODES * DDIM];
__device__ float         g_outg[NNODES * DDIM];
__device__ __nv_bfloat16 g_Lh[NNODES * DDIM], g_Ll[NNODES * DDIM];
__device__ __nv_bfloat16 g_X2h[NNODES * 384], g_X2l[NNODES * 384];
__device__ __nv_bfloat16 g_X3h[(size_t)NNODES * 256], g_X3l[(size_t)NNODES * 256];
// weights, split bf16, stored [n][k] (K-major rows); MLP hidden weights INTERLEAVED: n=2j+s (s=0 gate, 1 value)
__device__ __nv_bfloat16 gW13h[512 * 256], gW13l[512 * 256];
__device__ __nv_bfloat16 gWch[512 * 128],  gWcl[512 * 128];
__device__ __nv_bfloat16 gBo1h[128 * 256], gBo1l[128 * 256];
__device__ __nv_bfloat16 gBioh[256 * 128], gBiol[256 * 128];
__device__ __nv_bfloat16 gB2h[512 * 384],  gB2l[512 * 384];
__device__ __nv_bfloat16 gBo2h[128 * 256], gBo2l[128 * 256];

#define UPRE (g_big + (size_t)NR * 256)

// ======================= helpers =======================
__device__ __forceinline__ uint32_t smem_to_u32(const void* p) {
    uint32_t a;
    asm("{ .reg .u64 t; cvta.to.shared.u64 t, %1; cvt.u32.u64 %0, t; }" : "=r"(a) : "l"(p));
    return a;
}
__device__ __forceinline__ float gelu_tanh(float x) {
    float x3 = x * x * x;
    return 0.5f * x * (1.0f + tanhf(0.7978845608028654f * (x + 0.044715f * x3)));
}
__device__ __forceinline__ float sigm(float x) { return 1.0f / (1.0f + expf(-x)); }
__device__ __forceinline__ void split_bf16(float v, __nv_bfloat16& h, __nv_bfloat16& l) {
    h = __float2bfloat16(v);
    l = __float2bfloat16(v - __bfloat162float(h));
}
__device__ __forceinline__ void mma16816(float* c, const uint32_t* a, uint32_t b0, uint32_t b1) {
    asm volatile(
        "mma.sync.aligned.m16n8k16.row.col.f32.bf16.bf16.f32 "
        "{%0,%1,%2,%3}, {%4,%5,%6,%7}, {%8,%9}, {%0,%1,%2,%3};"
        : "+f"(c[0]), "+f"(c[1]), "+f"(c[2]), "+f"(c[3])
        : "r"(a[0]), "r"(a[1]), "r"(a[2]), "r"(a[3]), "r"(b0), "r"(b1));
}
__device__ __forceinline__ void ldsm4(uint32_t& r0, uint32_t& r1, uint32_t& r2, uint32_t& r3, uint32_t addr) {
    asm volatile("ldmatrix.sync.aligned.m8n8.x4.shared.b16 {%0,%1,%2,%3}, [%4];"
                 : "=r"(r0), "=r"(r1), "=r"(r2), "=r"(r3) : "r"(addr));
}
__device__ __forceinline__ void cp16(uint32_t dst, const void* src) {
    asm volatile("cp.async.cg.shared.global [%0], [%1], 16;" :: "r"(dst), "l"(src));
}
#define CP_COMMIT() asm volatile("cp.async.commit_group;" ::: "memory")
#define CP_WAIT(n)  asm volatile("cp.async.wait_group %0;" :: "n"(n) : "memory")

// ======================= split-bf16 GEMM (mma.sync + ldmatrix + cp.async) ==========
// C[m0:+128, n0:+128] = (Ah+Al)[M,K] @ (Bh+Bl)[N,K]^T; 3-term split AhBh+AhBl+AlBh.
// MODE 0: fp32 out.  MODE 1: sigmoid fp32 out.  MODE 2: fused gated-MLP epilogue
// (interleaved g|v cols; h = gelu(g+Cc+bg[j])*(v+Cc+bv[j]) -> split bf16 Oh/Ol, 256-wide).
template <int MODE>
__global__ void __launch_bounds__(256)
gemm_kernel(const __nv_bfloat16* __restrict__ Ah, const __nv_bfloat16* __restrict__ Al,
            int lda, int M, int K,
            const __nv_bfloat16* __restrict__ Bh, const __nv_bfloat16* __restrict__ Bl,
            float* __restrict__ C, int ldc,
            const float* __restrict__ Cc,
            const float* __restrict__ bgp, const float* __restrict__ bvp,
            __nv_bfloat16* __restrict__ Oh, __nv_bfloat16* __restrict__ Ol)
{
    extern __shared__ __align__(16) uint32_t dynsmem[];
    const uint32_t sbase = smem_to_u32(dynsmem);
    const int t = threadIdx.x, wid = t >> 5, lane = t & 31;
    const int lr = lane >> 2, lc = lane & 3;
    const int wm = wid & 3, wn = wid >> 2;
    const int m0 = blockIdx.x * 128, n0 = blockIdx.y * 128;

    float acc[2][8][4] = {};
    const int nch = K >> 5;

    auto issue = [&](int kc, int st) {
        uint32_t sb = sbase + (uint32_t)st * 40960u;
        #pragma unroll
        for (int i = t; i < 1024; i += 256) {     // A: planes h,l (128 rows x 32 bf16)
            int p = i >> 9, e = i & 511, r = e >> 2, q = e & 3;
            int row = m0 + r; if (row >= M) row = M - 1;   // clamp; rows >= M never written
            cp16(sb + (uint32_t)(p * 10240 + (r * SAS + q * 4) * 4),
                 (p ? Al : Ah) + (size_t)row * lda + kc * 32 + q * 8);
        }
        #pragma unroll
        for (int i = t; i < 1024; i += 256) {     // B: planes h,l
            int p = i >> 9, e = i & 511, r = e >> 2, q = e & 3;
            cp16(sb + (uint32_t)(20480 + p * 10240 + (r * SAS + q * 4) * 4),
                 (p ? Bl : Bh) + (size_t)(n0 + r) * K + kc * 32 + q * 8);
        }
    };

    issue(0, 0); CP_COMMIT();

    const int aRowL = lane & 15;
    const uint32_t aOffB = (uint32_t)((lane >> 4) << 4);
    const int bRowL = (lane & 7) + ((lane >> 4) << 3);
    const uint32_t bOffB = (uint32_t)(((lane >> 3) & 1) << 4);

    for (int kc = 0; kc < nch; kc++) {
        int st = kc & 1;
        if (kc + 1 < nch) { issue(kc + 1, st ^ 1); CP_COMMIT(); CP_WAIT(1); }
        else              { CP_WAIT(0); }
        __syncthreads();

        uint32_t stb = sbase + (uint32_t)st * 40960u;
        #pragma unroll
        for (int s = 0; s < 2; s++) {
            uint32_t ah[2][4], al[2][4];
            #pragma unroll
            for (int mf = 0; mf < 2; mf++) {
                uint32_t ra = (uint32_t)(((wm * 32 + mf * 16 + aRowL) * SAS + s * 8) * 4) + aOffB;
                ldsm4(ah[mf][0], ah[mf][1], ah[mf][2], ah[mf][3], stb + ra);
                ldsm4(al[mf][0], al[mf][1], al[mf][2], al[mf][3], stb + 10240 + ra);
            }
            #pragma unroll
            for (int nfp = 0; nfp < 4; nfp++) {
                uint32_t rb = (uint32_t)(((wn * 64 + nfp * 16 + bRowL) * SAS + s * 8) * 4) + bOffB;
                uint32_t bh[4], bl[4];
                ldsm4(bh[0], bh[1], bh[2], bh[3], stb + 20480 + rb);
                ldsm4(bl[0], bl[1], bl[2], bl[3], stb + 30720 + rb);
                #pragma unroll
                for (int mf = 0; mf < 2; mf++) {
                    mma16816(acc[mf][2 * nfp],     ah[mf], bh[0], bh[1]);
                    mma16816(acc[mf][2 * nfp],     ah[mf], bl[0], bl[1]);
                    mma16816(acc[mf][2 * nfp],     al[mf], bh[0], bh[1]);
                    mma16816(acc[mf][2 * nfp + 1], ah[mf], bh[2], bh[3]);
                    mma16816(acc[mf][2 * nfp + 1], ah[mf], bl[2], bl[3]);
                    mma16816(acc[mf][2 * nfp + 1], al[mf], bh[2], bh[3]);
                }
            }
        }
        __syncthreads();
    }

    // ---- epilogue ----
    #pragma unroll
    for (int mf = 0; mf < 2; mf++) {
        int r0 = m0 + wm * 32 + mf * 16 + lr;
        int r1 = r0 + 8;
        #pragma unroll
        for (int nf = 0; nf < 8; nf++) {
            int col = n0 + wn * 64 + nf * 8 + 2 * lc;
            float c0 = acc[mf][nf][0], c1 = acc[mf][nf][1];
            float c2 = acc[mf][nf][2], c3 = acc[mf][nf][3];
            if (MODE == 0) {
                if (r0 < M) *reinterpret_cast<float2*>(C + (size_t)r0 * ldc + col) = make_float2(c0, c1);
                if (r1 < M) *reinterpret_cast<float2*>(C + (size_t)r1 * ldc + col) = make_float2(c2, c3);
            } else if (MODE == 1) {
                if (r0 < M) *reinterpret_cast<float2*>(C + (size_t)r0 * ldc + col) = make_float2(sigm(c0), sigm(c1));
                if (r1 < M) *reinterpret_cast<float2*>(C + (size_t)r1 * ldc + col) = make_float2(sigm(c2), sigm(c3));
            } else {
                int j = col >> 1;
                float bgj = bgp[j], bvj = bvp[j];
                if (r0 < M) {
                    float cg = 0.f, cv = 0.f;
                    if (Cc) { float2 cc = *reinterpret_cast<const float2*>(Cc + (size_t)(r0 >> 4) * 512 + col); cg = cc.x; cv = cc.y; }
                    float h = gelu_tanh(c0 + cg + bgj) * (c1 + cv + bvj);
                    split_bf16(h, Oh[(size_t)r0 * 256 + j], Ol[(size_t)r0 * 256 + j]);
                }
                if (r1 < M) {
                    float cg = 0.f, cv = 0.f;
                    if (Cc) { float2 cc = *reinterpret_cast<const float2*>(Cc + (size_t)(r1 >> 4) * 512 + col); cg = cc.x; cv = cc.y; }
                    float h = gelu_tanh(c2 + cg + bgj) * (c3 + cv + bvj);
                    split_bf16(h, Oh[(size_t)r1 * 256 + j], Ol[(size_t)r1 * 256 + j]);
                }
            }
        }
    }
}

// ======================= elementwise / prep kernels =======================
__global__ void zero_out_kernel() {
    int i = blockIdx.x * blockDim.x + threadIdx.x;
    if (i < NNODES * DDIM) g_outg[i] = 0.0f;
}

// interleaved layouts: MLP hidden weight col n = 2j+s (s=0 gate from Wg, s=1 value from Wv)
__global__ void prep_weights_kernel(
    const float* __restrict__ Wg1, const float* __restrict__ Wv1,
    const float* __restrict__ Wo1, const float* __restrict__ Win,
    const float* __restrict__ Wou, const float* __restrict__ Wg2,
    const float* __restrict__ Wv2, const float* __restrict__ Wo2)
{
    int i = blockIdx.x * blockDim.x + threadIdx.x;
    int stride = gridDim.x * blockDim.x;
    for (int x = i; x < 512 * 256; x += stride) {   // W13i: k<128 -> wrow k (pair); else wrow 256+(k-128) (nbr)
        int n = x >> 8, k = x & 255;
        int j = n >> 1;
        const float* W = (n & 1) ? Wv1 : Wg1;
        int krow = (k < 128) ? k : (256 + (k - 128));
        split_bf16(W[krow * 256 + j], gW13h[x], gW13l[x]);
    }
    for (int x = i; x < 512 * 128; x += stride) {   // Wceni: wrows 128..255 (center local)
        int n = x >> 7, k = x & 127;
        int j = n >> 1;
        const float* W = (n & 1) ? Wv1 : Wg1;
        split_bf16(W[(128 + k) * 256 + j], gWch[x], gWcl[x]);
    }
    for (int x = i; x < 128 * 256; x += stride) {   // Bo1 [n][k]
        int n = x >> 8, k = x & 255;
        split_bf16(Wo1[k * 128 + n], gBo1h[x], gBo1l[x]);
    }
    for (int x = i; x < 256 * 128; x += stride) {   // Bio: n<128 Win else Wout
        int n = x >> 7, k = x & 127;
        const float* W = (n < 128) ? Win : Wou;
        split_bf16(W[k * 128 + (n & 127)], gBioh[x], gBiol[x]);
    }
    for (int x = i; x < 512 * 384; x += stride) {   // B2i interleaved
        int n = x / 384, k = x % 384;
        int j = n >> 1;
        const float* W = (n & 1) ? Wv2 : Wg2;
        split_bf16(W[k * 256 + j], gB2h[x], gB2l[x]);
    }
    for (int x = i; x < 128 * 256; x += stride) {   // Bo2
        int n = x >> 8, k = x & 255;
        split_bf16(Wo2[k * 128 + n], gBo2h[x], gBo2l[x]);
    }
}

__global__ void prep_A1_kernel(const float* __restrict__ pair, const float* __restrict__ local,
                               const int* __restrict__ nbrs)
{
    size_t i = (size_t)blockIdx.x * blockDim.x + threadIdx.x;
    if (i >= (size_t)NR * 256) return;
    int c = (int)(i & 255);
    size_t r = i >> 8;
    float v;
    if (c < 128) {
        v = pair[r * 128 + c];
    } else {
        int nb = nbrs[r];
        if (nb < 0) nb += NNODES;   // python wrap for -1
        v = local[(size_t)nb * 128 + (c - 128)];
    }
    split_bf16(v, g_A1h[i], g_A1l[i]);
}

__global__ void prep_L_kernel(const float* __restrict__ local) {
    int i = blockIdx.x * blockDim.x + threadIdx.x;
    if (i < NNODES * DDIM) split_bf16(local[i], g_Lh[i], g_Ll[i]);
}

__global__ void ln_pair_kernel(const float* __restrict__ pair, const float* __restrict__ bo,
                               const float* __restrict__ gp, const float* __restrict__ bp,
                               float* __restrict__ out)
{
    int row = blockIdx.x * 8 + (threadIdx.x >> 5);
    int lane = threadIdx.x & 31;
    if (row >= NR) return;
    const float* up = UPRE + (size_t)row * 128;
    float v[4], s = 0.0f, sq = 0.0f;
    #pragma unroll
    for (int j = 0; j < 4; j++) {
        int col = lane + j * 32;
        v[j] = up[col] + bo[col];
        s += v[j]; sq += v[j] * v[j];
    }
    #pragma unroll
    for (int o = 16; o > 0; o >>= 1) {
        s  += __shfl_xor_sync(0xffffffffu, s, o);
        sq += __shfl_xor_sync(0xffffffffu, sq, o);
    }
    float m = s * (1.0f / 128.0f);
    float var = sq * (1.0f / 128.0f) - m * m;
    float rstd = rsqrtf(var + 1e-5f);
    #pragma unroll
    for (int j = 0; j < 4; j++) {
        int col = lane + j * 32;
        float pu = (v[j] - m) * rstd * gp[col] + bp[col];
        g_pu[(size_t)row * 128 + col] = pu;
        out[(size_t)NNODES * 128 + (size_t)row * 128 + col] = pair[(size_t)row * 128 + col] + pu;
    }
}

__global__ void messages_kernel(const int* __restrict__ nbrs, const float* __restrict__ mask) {
    int n = blockIdx.x;
    int c = threadIdx.x;   // 128 threads
    float inc = 0.0f;
    #pragma unroll
    for (int kk = 0; kk < KNBR; kk++) {
        int row = n * KNBR + kk;
        int nb = nbrs[row];
        int nbw = (nb < 0) ? nb + NNODES : nb;
        bool valid = (nb != -1) && (mask[nbw] > 0.0f);
        if (valid) {
            float p  = g_pu[(size_t)row * 128 + c];
            float si = g_big[(size_t)row * 256 + c];          // pre-sigmoided in GEMM epilogue
            float so = g_big[(size_t)row * 256 + 128 + c];
            inc += si * p;
            atomicAdd(&g_outg[nbw * 128 + c], so * p);
        }
    }
    g_inc[n * 128 + c] = inc;
}

__global__ void prep_X2_kernel(const float* __restrict__ local) {
    int i = blockIdx.x * blockDim.x + threadIdx.x;
    if (i >= NNODES * 384) return;
    int k = i % 384;
    int r = i / 384;
    float v;
    if (k < 128)       v = local[(size_t)r * 128 + k];
    else if (k < 256)  v = g_inc[r * 128 + (k - 128)];
    else               v = g_outg[r * 128 + (k - 256)];
    split_bf16(v, g_X2h[i], g_X2l[i]);
}

__global__ void ln_local_kernel(const float* __restrict__ local, const float* __restrict__ bo,
                                const float* __restrict__ gl, const float* __restrict__ bl,
                                float* __restrict__ out)
{
    int row = blockIdx.x * 8 + (threadIdx.x >> 5);
    int lane = threadIdx.x & 31;
    if (row >= NNODES) return;
    const float* up = UPRE + (size_t)row * 128;
    float v[4], s = 0.0f, sq = 0.0f;
    #pragma unroll
    for (int j = 0; j < 4; j++) {
        int col = lane + j * 32;
        v[j] = up[col] + bo[col];
        s += v[j]; sq += v[j] * v[j];
    }
    #pragma unroll
    for (int o = 16; o > 0; o >>= 1) {
        s  += __shfl_xor_sync(0xffffffffu, s, o);
        sq += __shfl_xor_sync(0xffffffffu, sq, o);
    }
    float m = s * (1.0f / 128.0f);
    float var = sq * (1.0f / 128.0f) - m * m;
    float rstd = rsqrtf(var + 1e-5f);
    #pragma unroll
    for (int j = 0; j < 4; j++) {
        int col = lane + j * 32;
        float lu = (v[j] - m) * rstd * gl[col] + bl[col];
        out[(size_t)row * 128 + col] = local[(size_t)row * 128 + col] + lu;
    }
}

// ======================= launch =======================
extern "C" void kernel_launch(void* const* d_in, const int* in_sizes, int n_in,
                              void* d_out, int out_size)
{
    const float* local = (const float*)d_in[0];
    const float* pair  = (const float*)d_in[1];
    const int*   nbrs  = (const int*)  d_in[2];
    const float* mask  = (const float*)d_in[3];
    const float* Wg1 = (const float*)d_in[4];
    const float* bg1 = (const float*)d_in[5];
    const float* Wv1 = (const float*)d_in[6];
    const float* bv1 = (const float*)d_in[7];
    const float* Wo1 = (const float*)d_in[8];
    const float* bo1 = (const float*)d_in[9];
    const float* gp  = (const float*)d_in[10];
    const float* bp  = (const float*)d_in[11];
    const float* Win = (const float*)d_in[12];
    const float* Wou = (const float*)d_in[13];
    const float* Wg2 = (const float*)d_in[14];
    const float* bg2 = (const float*)d_in[15];
    const float* Wv2 = (const float*)d_in[16];
    const float* bv2 = (const float*)d_in[17];
    const float* Wo2 = (const float*)d_in[18];
    const float* bo2 = (const float*)d_in[19];
    const float* gl  = (const float*)d_in[20];
    const float* bl  = (const float*)d_in[21];
    float* out = (float*)d_out;

    cudaFuncSetAttribute(gemm_kernel<0>, cudaFuncAttributeMaxDynamicSharedMemorySize, DSMEM);
    cudaFuncSetAttribute(gemm_kernel<1>, cudaFuncAttributeMaxDynamicSharedMemorySize, DSMEM);
    cudaFuncSetAttribute(gemm_kernel<2>, cudaFuncAttributeMaxDynamicSharedMemorySize, DSMEM);

    float *gbig, *gcc;
    cudaGetSymbolAddress((void**)&gbig, g_big);
    cudaGetSymbolAddress((void**)&gcc,  g_Cc);
    __nv_bfloat16 *a1h, *a1l, *hh, *hl, *lh, *ll, *x2h, *x2l, *x3h, *x3l;
    cudaGetSymbolAddress((void**)&a1h, g_A1h); cudaGetSymbolAddress((void**)&a1l, g_A1l);
    cudaGetSymbolAddress((void**)&hh,  g_Hh);  cudaGetSymbolAddress((void**)&hl,  g_Hl);
    cudaGetSymbolAddress((void**)&lh,  g_Lh);  cudaGetSymbolAddress((void**)&ll,  g_Ll);
    cudaGetSymbolAddress((void**)&x2h, g_X2h); cudaGetSymbolAddress((void**)&x2l, g_X2l);
    cudaGetSymbolAddress((void**)&x3h, g_X3h); cudaGetSymbolAddress((void**)&x3l, g_X3l);
    __nv_bfloat16 *w13h, *w13l, *wch, *wcl, *bo1h, *bo1l, *bioh, *biol, *b2h, *b2l, *bo2h, *bo2l;
    cudaGetSymbolAddress((void**)&w13h, gW13h); cudaGetSymbolAddress((void**)&w13l, gW13l);
    cudaGetSymbolAddress((void**)&wch,  gWch);  cudaGetSymbolAddress((void**)&wcl,  gWcl);
    cudaGetSymbolAddress((void**)&bo1h, gBo1h); cudaGetSymbolAddress((void**)&bo1l, gBo1l);
    cudaGetSymbolAddress((void**)&bioh, gBioh); cudaGetSymbolAddress((void**)&biol, gBiol);
    cudaGetSymbolAddress((void**)&b2h,  gB2h);  cudaGetSymbolAddress((void**)&b2l,  gB2l);
    cudaGetSymbolAddress((void**)&bo2h, gBo2h); cudaGetSymbolAddress((void**)&bo2l, gBo2l);
    float* upre = gbig + (size_t)NR * 256;

    // 1) prep
    zero_out_kernel<<<(NNODES * DDIM + 255) / 256, 256>>>();
    prep_weights_kernel<<<512, 256>>>(Wg1, Wv1, Wo1, Win, Wou, Wg2, Wv2, Wo2);
    prep_A1_kernel<<<(int)(((size_t)NR * 256 + 255) / 256), 256>>>(pair, local, nbrs);
    prep_L_kernel<<<(NNODES * DDIM + 255) / 256, 256>>>(local);

    // 2) Cc = local @ Wceni (interleaved) : [20000,128]x[128,512]
    gemm_kernel<0><<<dim3(157, 4), 256, DSMEM>>>(lh, ll, 128, NNODES, 128, wch, wcl,
                                                 gcc, 512, nullptr, nullptr, nullptr, nullptr, nullptr);
    // 3) H = gelu(A1@W13i + Cc + bg) * (… + bv)  -> split bf16 Hh/Hl (fused epilogue)
    gemm_kernel<2><<<dim3(2500, 4), 256, DSMEM>>>(a1h, a1l, 256, NR, 256, w13h, w13l,
                                                  nullptr, 0, gcc, bg1, bv1, hh, hl);
    // 4) u_pre = H @ Bo1 : [320000,256]x[256,128] -> UPRE
    gemm_kernel<0><<<dim3(2500, 1), 256, DSMEM>>>(hh, hl, 256, NR, 256, bo1h, bo1l,
                                                  upre, 128, nullptr, nullptr, nullptr, nullptr, nullptr);
    // 5) gates S = sigmoid(A1.pair @ [Win||Wout]) : [320000,128]x[128,256] (fused sigmoid)
    gemm_kernel<1><<<dim3(2500, 2), 256, DSMEM>>>(a1h, a1l, 256, NR, 128, bioh, biol,
                                                  gbig, 256, nullptr, nullptr, nullptr, nullptr, nullptr);
    // 6) LN pair + residual pair output + store pu
    ln_pair_kernel<<<(NR + 7) / 8, 256>>>(pair, bo1, gp, bp, out);
    // 7) incoming sum + outgoing atomic scatter
    messages_kernel<<<NNODES, 128>>>(nbrs, mask);
    // 8) local features
    prep_X2_kernel<<<(NNODES * 384 + 255) / 256, 256>>>(local);
    // 9) X3 = gelu/value fused local MLP hidden : [20000,384]x[384,512] -> X3h/X3l
    gemm_kernel<2><<<dim3(157, 4), 256, DSMEM>>>(x2h, x2l, 384, NNODES, 384, b2h, b2l,
                                                 nullptr, 0, nullptr, bg2, bv2, x3h, x3l);
    // 10) u2_pre = X3 @ Bo2 : [20000,256]x[256,128] -> UPRE (reuse)
    gemm_kernel<0><<<dim3(157, 1), 256, DSMEM>>>(x3h, x3l, 256, NNODES, 256, bo2h, bo2l,
                                                 upre, 128, nullptr, nullptr, nullptr, nullptr, nullptr);
    // 11) LN local + residual local output
    ln_local_kernel<<<(NNODES + 7) / 8, 256>>>(local, bo2, gl, bl, out);
}